// round 11
// baseline (speedup 1.0000x reference)
#include <cuda_runtime.h>
#include <cuda_bf16.h>
#include <math_constants.h>
#include <limits.h>

// Segment-max pooling, sorted ids (N rows x 32 ch -> M segments).
// One warp owns CHUNK=64 rows. The warp's 8KB feat slab is staged into shared
// memory via two cp.async.bulk (UBLKCP) copies completing on per-warp
// mbarriers: the full chunk is in flight with zero register pressure and no
// LDG scoreboard coupling. Boundary logic (64-bit ballot mask, batch fast
// path, responsible-warp tail scan, gap zeroing) is identical to the best
// LDG variant; consumption is conflict-free LDS (lane = channel).

#define CHUNK 64
#define BATCH 8
#define WARPS_PER_BLOCK 4
#define HALF_BYTES 4096                  // 32 rows * 128 B
#define DATA_OFF   128                   // mbar region + pad

typedef unsigned long long ull;

__device__ __forceinline__ unsigned smem_u32(const void* p) {
    unsigned a;
    asm("{ .reg .u64 t; cvta.to.shared.u64 t, %1; cvt.u32.u64 %0, t; }"
        : "=r"(a) : "l"(p));
    return a;
}

__device__ __forceinline__ void mbar_wait(unsigned mbar, unsigned parity) {
    asm volatile(
        "{\n\t"
        ".reg .pred P;\n\t"
        "WL_%=:\n\t"
        "mbarrier.try_wait.parity.acquire.cta.shared::cta.b64 P, [%0], %1, 0x989680;\n\t"
        "@P bra.uni WD_%=;\n\t"
        "bra.uni WL_%=;\n\t"
        "WD_%=:\n\t"
        "}"
        :: "r"(mbar), "r"(parity) : "memory");
}

__global__ __launch_bounds__(128) void seg_max_kernel(
    const float* __restrict__ feat,
    const int*   __restrict__ ids,
    float*       __restrict__ out,
    int N, int M)
{
    extern __shared__ char smem[];
    const unsigned FULL = 0xFFFFFFFFu;
    const int lane  = threadIdx.x & 31;
    const int wib   = threadIdx.x >> 5;                 // warp in block
    const int warp  = blockIdx.x * WARPS_PER_BLOCK + wib;

    const int r0 = warp * CHUNK;                        // < 4M, fits int
    if (r0 >= N) return;
    const int nrows = (N - r0 < CHUNK) ? (N - r0) : CHUNK;

    const unsigned mbar0 = smem_u32(smem) + wib * 16;
    const unsigned mbar1 = mbar0 + 8;
    float* buf = (float*)(smem + DATA_OFF + wib * (2 * HALF_BYTES));

    int   cur;
    bool  resp = false;
    float m    = -CUDART_INF_F;

    if (nrows == CHUNK) {
        // Stage the chunk: two 4KB bulk copies, issued before anything else.
        if (lane == 0) {
            asm volatile("mbarrier.init.shared.b64 [%0], 1;" :: "r"(mbar0) : "memory");
            asm volatile("mbarrier.init.shared.b64 [%0], 1;" :: "r"(mbar1) : "memory");
            asm volatile("fence.proxy.async.shared::cta;" ::: "memory");
            asm volatile("mbarrier.arrive.expect_tx.shared.b64 _, [%0], %1;"
                         :: "r"(mbar0), "r"(HALF_BYTES) : "memory");
            asm volatile("cp.async.bulk.shared::cluster.global.mbarrier::complete_tx::bytes "
                         "[%0], [%1], %2, [%3];"
                         :: "r"(smem_u32(buf)),
                            "l"(feat + (unsigned)r0 * 32u),
                            "r"(HALF_BYTES), "r"(mbar0) : "memory");
            asm volatile("mbarrier.arrive.expect_tx.shared.b64 _, [%0], %1;"
                         :: "r"(mbar1), "r"(HALF_BYTES) : "memory");
            asm volatile("cp.async.bulk.shared::cluster.global.mbarrier::complete_tx::bytes "
                         "[%0], [%1], %2, [%3];"
                         :: "r"(smem_u32(buf) + HALF_BYTES),
                            "l"(feat + (unsigned)(r0 + 32) * 32u),
                            "r"(HALF_BYTES), "r"(mbar1) : "memory");
        }
        __syncwarp();

        // Meanwhile: ids (coalesced) + tail prefetch + boundary mask.
        int id_lo = ids[r0 + lane];
        int id_hi = ids[r0 + 32 + lane];
        int idn0  = (r0 + CHUNK + lane < N) ? ids[r0 + CHUNK + lane] : INT_MAX;
        const int prev_id = (r0 > 0) ? ids[r0 - 1] : -1;
        cur = prev_id;

        int p = __shfl_up_sync(FULL, id_lo, 1);
        if (lane == 0) p = prev_id;
        unsigned mlo = __ballot_sync(FULL, id_lo != p);
        int s = __shfl_sync(FULL, id_lo, 31);
        p = __shfl_up_sync(FULL, id_hi, 1);
        if (lane == 0) p = s;
        unsigned mhi = __ballot_sync(FULL, id_hi != p);
        const ull bmask = (ull)mlo | ((ull)mhi << 32);

        mbar_wait(mbar0, 0);
        #pragma unroll
        for (int base = 0; base < CHUNK; base += BATCH) {
            if (base == 32) mbar_wait(mbar1, 0);

            float v[BATCH];
            #pragma unroll
            for (int j = 0; j < BATCH; ++j)
                v[j] = buf[(base + j) * 32 + lane];     // conflict-free LDS

            const unsigned bb = (unsigned)(bmask >> base) & 0xFFu;
            if (bb == 0u) {                             // uniform: no boundary
                float a = fmaxf(v[0], v[1]);
                float b = fmaxf(v[2], v[3]);
                float c = fmaxf(v[4], v[5]);
                float d = fmaxf(v[6], v[7]);
                m = fmaxf(m, fmaxf(fmaxf(a, b), fmaxf(c, d)));
            } else {
                #pragma unroll
                for (int j = 0; j < BATCH; ++j) {
                    if ((bb >> j) & 1u) {               // uniform (mask bit)
                        const int i = base + j;
                        int nid = __shfl_sync(FULL, (i < 32) ? id_lo : id_hi,
                                              i & 31);
                        if (resp) {
                            out[cur * 32 + lane] = m;
                            for (int g = cur + 1; g < nid; ++g)
                                out[g * 32 + lane] = 0.0f;
                        }
                        cur  = nid;
                        m    = -CUDART_INF_F;
                        resp = true;
                    }
                    m = fmaxf(m, v[j]);
                }
            }
        }

        // Finish the last segment we own (may continue past the chunk end).
        int r = r0 + CHUNK;
        if (resp) {
            bool first = true;
            while (r < N) {                             // uniform condition
                int rl = r + lane;
                int idn = first ? idn0 : ((rl < N) ? ids[rl] : INT_MAX);
                first = false;
                unsigned diff = __ballot_sync(FULL, idn != cur);
                int k = diff ? (__ffs(diff) - 1) : 32;
                for (int j = 0; j < k; ++j)             // independent LDGs
                    m = fmaxf(m, __ldcs(&feat[(unsigned)(r + j) * 32u + lane]));
                r += k;
                if (k < 32) break;
            }
            out[cur * 32 + lane] = m;
            int next_id = (r < N) ? ids[r] : M;
            for (int g = cur + 1; g < next_id; ++g)
                out[g * 32 + lane] = 0.0f;
        }
    } else {
        // Ragged last chunk: direct-LDG scalar path (at most one warp).
        int id_lo = (lane < nrows)      ? ids[r0 + lane]      : 0;
        int id_hi = (32 + lane < nrows) ? ids[r0 + 32 + lane] : 0;
        const int prev_id = (r0 > 0) ? ids[r0 - 1] : -1;
        cur = prev_id;

        const float* fptr = feat + (unsigned)r0 * 32u + (unsigned)lane;
        for (int i = 0; i < nrows; ++i) {
            int id = __shfl_sync(FULL, (i < 32) ? id_lo : id_hi, i & 31);
            if (id != cur) {
                if (resp) {
                    out[cur * 32 + lane] = m;
                    for (int g = cur + 1; g < id; ++g)
                        out[g * 32 + lane] = 0.0f;
                }
                cur  = id;
                m    = -CUDART_INF_F;
                resp = true;
            }
            m = fmaxf(m, fptr[i * 32]);
        }
        if (resp) {
            out[cur * 32 + lane] = m;
            for (int g = cur + 1; g < M; ++g)           // trailing gap
                out[g * 32 + lane] = 0.0f;
        }
    }

    // Leading gap: segments before ids[0] are empty.
    if (r0 == 0) {
        int first_id = ids[0];
        for (int g = 0; g < first_id; ++g)
            out[g * 32 + lane] = 0.0f;
    }
}

extern "C" void kernel_launch(void* const* d_in, const int* in_sizes, int n_in,
                              void* d_out, int out_size) {
    const float* feat = (const float*)d_in[0];
    const int*   ids  = (const int*)d_in[1];
    float*       out  = (float*)d_out;

    const int N = in_sizes[1];
    const int M = out_size / 32;

    const int warps  = (N + CHUNK - 1) / CHUNK;
    const int blocks = (warps + WARPS_PER_BLOCK - 1) / WARPS_PER_BLOCK;
    const int smem_bytes = DATA_OFF + WARPS_PER_BLOCK * 2 * HALF_BYTES;

    seg_max_kernel<<<blocks, 128, smem_bytes>>>(feat, ids, out, N, M);
}

// round 12
// speedup vs baseline: 1.0514x; 1.0514x over previous
#include <cuda_runtime.h>
#include <cuda_bf16.h>
#include <math_constants.h>
#include <limits.h>

// Segment-max pooling, sorted ids (N rows x 32 ch -> M segments).
// One warp owns CHUNK=64 rows, streamed through TWO 2KB smem buffers filled by
// cp.async.bulk (per-warp mbarriers, double-buffered: stage s uses buffer s&1
// at parity s>>1; after consuming, lane0 re-arms the buffer for stage s+2).
// 16.5KB smem/block -> 13 blocks/SM -> 81% occupancy AND full-chunk bytes in
// flight with no register cost. Boundary logic: 64-bit ballot mask, batch
// fast path, responsible-warp tail scan, gap zeroing (as the best LDG kernel).

#define CHUNK 64
#define ROWS_PER_STAGE 16
#define STAGE_BYTES 2048
#define WARPS_PER_BLOCK 4
#define DATA_OFF 128

typedef unsigned long long ull;

__device__ __forceinline__ unsigned smem_u32(const void* p) {
    unsigned a;
    asm("{ .reg .u64 t; cvta.to.shared.u64 t, %1; cvt.u32.u64 %0, t; }"
        : "=r"(a) : "l"(p));
    return a;
}

__device__ __forceinline__ void mbar_wait(unsigned mbar, unsigned parity) {
    asm volatile(
        "{\n\t"
        ".reg .pred P;\n\t"
        "WL_%=:\n\t"
        "mbarrier.try_wait.parity.acquire.cta.shared::cta.b64 P, [%0], %1, 0x989680;\n\t"
        "@P bra.uni WD_%=;\n\t"
        "bra.uni WL_%=;\n\t"
        "WD_%=:\n\t"
        "}"
        :: "r"(mbar), "r"(parity) : "memory");
}

__device__ __forceinline__ void stage_copy(unsigned mbar, unsigned dst,
                                           const float* src) {
    asm volatile("fence.proxy.async.shared::cta;" ::: "memory");
    asm volatile("mbarrier.arrive.expect_tx.shared.b64 _, [%0], %1;"
                 :: "r"(mbar), "r"(STAGE_BYTES) : "memory");
    asm volatile("cp.async.bulk.shared::cluster.global.mbarrier::complete_tx::bytes "
                 "[%0], [%1], %2, [%3];"
                 :: "r"(dst), "l"(src), "r"(STAGE_BYTES), "r"(mbar) : "memory");
}

__global__ __launch_bounds__(128, 13) void seg_max_kernel(
    const float* __restrict__ feat,
    const int*   __restrict__ ids,
    float*       __restrict__ out,
    int N, int M)
{
    extern __shared__ char smem[];
    const unsigned FULL = 0xFFFFFFFFu;
    const int lane = threadIdx.x & 31;
    const int wib  = threadIdx.x >> 5;
    const int warp = blockIdx.x * WARPS_PER_BLOCK + wib;

    const int r0 = warp * CHUNK;                        // < 4M, fits int
    if (r0 >= N) return;
    const int nrows = (N - r0 < CHUNK) ? (N - r0) : CHUNK;

    const unsigned mb0  = smem_u32(smem) + wib * 16;    // two mbars, 8B each
    float*   buf  = (float*)(smem + DATA_OFF + wib * (2 * STAGE_BYTES));
    unsigned bufa = smem_u32(buf);

    int   cur;
    bool  resp = false;
    float m    = -CUDART_INF_F;

    if (nrows == CHUNK) {
        // Arm both buffers with the first two 16-row stages.
        if (lane == 0) {
            asm volatile("mbarrier.init.shared.b64 [%0], 1;" :: "r"(mb0)     : "memory");
            asm volatile("mbarrier.init.shared.b64 [%0], 1;" :: "r"(mb0 + 8) : "memory");
            stage_copy(mb0,     bufa,               feat + (unsigned)r0 * 32u);
            stage_copy(mb0 + 8, bufa + STAGE_BYTES, feat + (unsigned)(r0 + 16) * 32u);
        }
        __syncwarp();

        // While data streams in: ids (coalesced), tail prefetch, boundary mask.
        int id_lo = ids[r0 + lane];
        int id_hi = ids[r0 + 32 + lane];
        int idn0  = (r0 + CHUNK + lane < N) ? ids[r0 + CHUNK + lane] : INT_MAX;
        const int prev_id = (r0 > 0) ? ids[r0 - 1] : -1;
        cur = prev_id;

        int p = __shfl_up_sync(FULL, id_lo, 1);
        if (lane == 0) p = prev_id;
        unsigned mlo = __ballot_sync(FULL, id_lo != p);
        int s = __shfl_sync(FULL, id_lo, 31);
        p = __shfl_up_sync(FULL, id_hi, 1);
        if (lane == 0) p = s;
        unsigned mhi = __ballot_sync(FULL, id_hi != p);
        const ull bmask = (ull)mlo | ((ull)mhi << 32);

        #pragma unroll
        for (int stage = 0; stage < 4; ++stage) {
            const unsigned mbar = mb0 + (stage & 1) * 8;
            mbar_wait(mbar, stage >> 1);
            const float* sb = buf + (stage & 1) * (STAGE_BYTES / 4);

            #pragma unroll
            for (int half = 0; half < 2; ++half) {
                const int base = stage * ROWS_PER_STAGE + half * 8;

                float v[8];
                #pragma unroll
                for (int j = 0; j < 8; ++j)
                    v[j] = sb[(half * 8 + j) * 32 + lane];   // conflict-free

                const unsigned bb = (unsigned)(bmask >> base) & 0xFFu;
                if (bb == 0u) {                       // uniform: no boundary
                    float a = fmaxf(v[0], v[1]);
                    float b = fmaxf(v[2], v[3]);
                    float c = fmaxf(v[4], v[5]);
                    float d = fmaxf(v[6], v[7]);
                    m = fmaxf(m, fmaxf(fmaxf(a, b), fmaxf(c, d)));
                } else {
                    #pragma unroll
                    for (int j = 0; j < 8; ++j) {
                        if ((bb >> j) & 1u) {         // uniform (mask bit)
                            const int i = base + j;
                            int nid = __shfl_sync(FULL,
                                                  (i < 32) ? id_lo : id_hi,
                                                  i & 31);
                            if (resp) {
                                out[cur * 32 + lane] = m;
                                for (int g = cur + 1; g < nid; ++g)
                                    out[g * 32 + lane] = 0.0f;
                            }
                            cur  = nid;
                            m    = -CUDART_INF_F;
                            resp = true;
                        }
                        m = fmaxf(m, v[j]);
                    }
                }
            }

            // Re-arm this buffer with stage+2 (same mbarrier, next parity).
            if (stage < 2 && lane == 0)
                stage_copy(mbar, bufa + (stage & 1) * STAGE_BYTES,
                           feat + (unsigned)(r0 + (stage + 2) * ROWS_PER_STAGE) * 32u);
        }

        // Finish the last segment we own (may continue past the chunk end).
        int r = r0 + CHUNK;
        if (resp) {
            bool first = true;
            while (r < N) {                           // uniform condition
                int rl = r + lane;
                int idn = first ? idn0 : ((rl < N) ? ids[rl] : INT_MAX);
                first = false;
                unsigned diff = __ballot_sync(FULL, idn != cur);
                int k = diff ? (__ffs(diff) - 1) : 32;
                for (int j = 0; j < k; ++j)           // independent LDGs
                    m = fmaxf(m, __ldcs(&feat[(unsigned)(r + j) * 32u + lane]));
                r += k;
                if (k < 32) break;
            }
            out[cur * 32 + lane] = m;
            int next_id = (r < N) ? ids[r] : M;
            for (int g = cur + 1; g < next_id; ++g)
                out[g * 32 + lane] = 0.0f;
        }
    } else {
        // Ragged last chunk: direct-LDG scalar path (at most one warp).
        int id_lo = (lane < nrows)      ? ids[r0 + lane]      : 0;
        int id_hi = (32 + lane < nrows) ? ids[r0 + 32 + lane] : 0;
        const int prev_id = (r0 > 0) ? ids[r0 - 1] : -1;
        cur = prev_id;

        const float* fptr = feat + (unsigned)r0 * 32u + (unsigned)lane;
        for (int i = 0; i < nrows; ++i) {
            int id = __shfl_sync(FULL, (i < 32) ? id_lo : id_hi, i & 31);
            if (id != cur) {
                if (resp) {
                    out[cur * 32 + lane] = m;
                    for (int g = cur + 1; g < id; ++g)
                        out[g * 32 + lane] = 0.0f;
                }
                cur  = id;
                m    = -CUDART_INF_F;
                resp = true;
            }
            m = fmaxf(m, fptr[i * 32]);
        }
        if (resp) {
            out[cur * 32 + lane] = m;
            for (int g = cur + 1; g < M; ++g)         // trailing gap
                out[g * 32 + lane] = 0.0f;
        }
    }

    // Leading gap: segments before ids[0] are empty.
    if (r0 == 0) {
        int first_id = ids[0];
        for (int g = 0; g < first_id; ++g)
            out[g * 32 + lane] = 0.0f;
    }
}

extern "C" void kernel_launch(void* const* d_in, const int* in_sizes, int n_in,
                              void* d_out, int out_size) {
    const float* feat = (const float*)d_in[0];
    const int*   ids  = (const int*)d_in[1];
    float*       out  = (float*)d_out;

    const int N = in_sizes[1];
    const int M = out_size / 32;

    const int warps  = (N + CHUNK - 1) / CHUNK;
    const int blocks = (warps + WARPS_PER_BLOCK - 1) / WARPS_PER_BLOCK;
    const int smem_bytes = DATA_OFF + WARPS_PER_BLOCK * 2 * STAGE_BYTES;

    seg_max_kernel<<<blocks, 128, smem_bytes>>>(feat, ids, out, N, M);
}

// round 13
// speedup vs baseline: 1.1436x; 1.0878x over previous
#include <cuda_runtime.h>
#include <cuda_bf16.h>
#include <math_constants.h>
#include <limits.h>

// Segment-max pooling, sorted ids (N rows x 32 ch -> M segments).
// One warp owns CHUNK=64 rows; lane = channel (scalar LDG.32).
// Boundaries precomputed as a 64-bit ballot mask. BATCH=16 independent LDGs
// per inner iteration (2KB in flight per warp) with regs capped at 36 via
// __launch_bounds__(256,7): 87.5% occupancy. Full batches before the warp's
// first boundary are skipped (uniform branch); partial batch loads pollute m
// harmlessly (discarded at first flush, resp==false). Tail ids prefetched.

#define CHUNK 64
#define BATCH 16

typedef unsigned long long ull;

__global__ __launch_bounds__(256, 7) void seg_max_kernel(
    const float* __restrict__ feat,
    const int*   __restrict__ ids,
    float*       __restrict__ out,
    int N, int M)
{
    const unsigned FULL = 0xFFFFFFFFu;
    const int lane = threadIdx.x & 31;
    const int warp = blockIdx.x * (blockDim.x >> 5) + (threadIdx.x >> 5);

    const int r0 = warp * CHUNK;               // < 4M, fits int
    if (r0 >= N) return;
    const int nrows = (N - r0 < CHUNK) ? (N - r0) : CHUNK;

    // Coalesced chunk ids + prefetch of the 32 ids after the chunk.
    int id_lo = (lane < nrows)      ? ids[r0 + lane]      : 0;
    int id_hi = (32 + lane < nrows) ? ids[r0 + 32 + lane] : 0;
    int idn0  = (r0 + CHUNK + lane < N) ? ids[r0 + CHUNK + lane] : INT_MAX;
    const int prev_id = (r0 > 0) ? ids[r0 - 1] : -1;

    int   cur  = prev_id;
    bool  resp = false;
    float m    = -CUDART_INF_F;

    const float* fptr = feat + (unsigned)r0 * 32u + (unsigned)lane;

    if (nrows == CHUNK) {
        // 64-bit boundary mask: bit i set iff ids[r0+i] != ids[r0+i-1].
        int p = __shfl_up_sync(FULL, id_lo, 1);
        if (lane == 0) p = prev_id;
        unsigned mlo = __ballot_sync(FULL, id_lo != p);

        int s = __shfl_sync(FULL, id_lo, 31);
        p = __shfl_up_sync(FULL, id_hi, 1);
        if (lane == 0) p = s;
        unsigned mhi = __ballot_sync(FULL, id_hi != p);

        const ull bmask = (ull)mlo | ((ull)mhi << 32);
        // First row we own; full batches before it are skipped entirely.
        const int i0 = bmask ? (__ffsll((long long)bmask) - 1) : CHUNK;

        #pragma unroll
        for (int base = 0; base < CHUNK; base += BATCH) {
            if (base + BATCH <= i0) continue;   // uniform: fully skipped

            // Unconditional batch of independent LDG.32 (pre-i0 rows in the
            // partial batch pollute m harmlessly: discarded at first flush).
            float v[BATCH];
            #pragma unroll
            for (int j = 0; j < BATCH; ++j)
                v[j] = __ldcs(&fptr[(base + j) * 32]);

            const unsigned bb = (unsigned)(bmask >> base) & 0xFFFFu;
            if (bb == 0u) {                     // uniform: no boundary
                float t0 = fmaxf(fmaxf(v[0],  v[1]),  fmaxf(v[2],  v[3]));
                float t1 = fmaxf(fmaxf(v[4],  v[5]),  fmaxf(v[6],  v[7]));
                float t2 = fmaxf(fmaxf(v[8],  v[9]),  fmaxf(v[10], v[11]));
                float t3 = fmaxf(fmaxf(v[12], v[13]), fmaxf(v[14], v[15]));
                m = fmaxf(m, fmaxf(fmaxf(t0, t1), fmaxf(t2, t3)));
            } else {
                #pragma unroll
                for (int j = 0; j < BATCH; ++j) {
                    if ((bb >> j) & 1u) {       // uniform (mask bit)
                        const int i = base + j;
                        int nid = __shfl_sync(FULL, (i < 32) ? id_lo : id_hi,
                                              i & 31);
                        if (resp) {
                            out[cur * 32 + lane] = m;
                            for (int g = cur + 1; g < nid; ++g)
                                out[g * 32 + lane] = 0.0f;
                        }
                        cur  = nid;
                        m    = -CUDART_INF_F;
                        resp = true;
                    }
                    m = fmaxf(m, v[j]);
                }
            }
        }
    } else {
        // Ragged last chunk: scalar path (one warp in the grid).
        for (int i = 0; i < nrows; ++i) {
            int id = __shfl_sync(FULL, (i < 32) ? id_lo : id_hi, i & 31);
            if (id != cur) {
                if (resp) {
                    out[cur * 32 + lane] = m;
                    for (int g = cur + 1; g < id; ++g)
                        out[g * 32 + lane] = 0.0f;
                }
                cur  = id;
                m    = -CUDART_INF_F;
                resp = true;
            }
            m = fmaxf(m, fptr[i * 32]);
        }
    }

    // Finish the last segment we own: it may continue past the chunk end.
    int r = r0 + nrows;
    if (resp) {
        bool first = (nrows == CHUNK);
        while (r < N) {                         // uniform condition
            int rl = r + lane;
            int idn = first ? idn0 : ((rl < N) ? ids[rl] : INT_MAX);
            first = false;
            unsigned diff = __ballot_sync(FULL, idn != cur);
            int k = diff ? (__ffs(diff) - 1) : 32;   // continuation rows
            for (int j = 0; j < k; ++j)              // independent loads
                m = fmaxf(m, __ldcs(&feat[(unsigned)(r + j) * 32u + lane]));
            r += k;
            if (k < 32) break;
        }
        out[cur * 32 + lane] = m;
        int next_id = (r < N) ? ids[r] : M;
        for (int g = cur + 1; g < next_id; ++g)
            out[g * 32 + lane] = 0.0f;
    }

    // Leading gap: segments before ids[0] are empty.
    if (r0 == 0) {
        int first_id = ids[0];
        for (int g = 0; g < first_id; ++g)
            out[g * 32 + lane] = 0.0f;
    }
}

extern "C" void kernel_launch(void* const* d_in, const int* in_sizes, int n_in,
                              void* d_out, int out_size) {
    const float* feat = (const float*)d_in[0];
    const int*   ids  = (const int*)d_in[1];
    float*       out  = (float*)d_out;

    const int N = in_sizes[1];
    const int M = out_size / 32;

    const int warps   = (N + CHUNK - 1) / CHUNK;
    const int threads = 256;
    const int blocks  = (warps * 32 + threads - 1) / threads;

    seg_max_kernel<<<blocks, threads>>>(feat, ids, out, N, M);
}

// round 14
// speedup vs baseline: 1.1540x; 1.0091x over previous
#include <cuda_runtime.h>
#include <cuda_bf16.h>
#include <math_constants.h>
#include <limits.h>

// Segment-max pooling, sorted ids (N rows x 32 ch -> M segments).
// One warp owns CHUNK=128 rows; lane = channel (scalar LDG.32, BATCH=8).
// Boundaries precomputed as a 128-bit ballot mask; per-chunk fixed costs
// (mask build, tail-scan round trip, overhang re-reads) amortized over 2x
// rows vs CHUNK=64. regs pinned to 32 via __launch_bounds__(256,8) -- the
// known fix for the CHUNK=128 occupancy failure. Full batches before the
// warp's first boundary are skipped (uniform); partial-batch pollution is
// discarded at the first flush (resp==false). Tail ids prefetched.

#define CHUNK 128
#define BATCH 8

typedef unsigned long long ull;

__global__ __launch_bounds__(256, 8) void seg_max_kernel(
    const float* __restrict__ feat,
    const int*   __restrict__ ids,
    float*       __restrict__ out,
    int N, int M)
{
    const unsigned FULL = 0xFFFFFFFFu;
    const int lane = threadIdx.x & 31;
    const int warp = blockIdx.x * (blockDim.x >> 5) + (threadIdx.x >> 5);

    const int r0 = warp * CHUNK;               // < 4M, fits int
    if (r0 >= N) return;
    const int nrows = (N - r0 < CHUNK) ? (N - r0) : CHUNK;

    // Coalesced chunk ids (4 x 32) + prefetch of the 32 ids after the chunk.
    int idr0 = (lane < nrows)       ? ids[r0 + lane]       : 0;
    int idr1 = (32  + lane < nrows) ? ids[r0 + 32  + lane] : 0;
    int idr2 = (64  + lane < nrows) ? ids[r0 + 64  + lane] : 0;
    int idr3 = (96  + lane < nrows) ? ids[r0 + 96  + lane] : 0;
    int idn0 = (r0 + CHUNK + lane < N) ? ids[r0 + CHUNK + lane] : INT_MAX;
    const int prev_id = (r0 > 0) ? ids[r0 - 1] : -1;

    int   cur  = prev_id;
    bool  resp = false;
    float m    = -CUDART_INF_F;

    const float* fptr = feat + (unsigned)r0 * 32u + (unsigned)lane;

    if (nrows == CHUNK) {
        // 128-bit boundary mask: bit i set iff ids[r0+i] != ids[r0+i-1].
        unsigned mk0, mk1, mk2, mk3;
        {
            int p, s;
            p = __shfl_up_sync(FULL, idr0, 1); if (lane == 0) p = prev_id;
            mk0 = __ballot_sync(FULL, idr0 != p);
            s = __shfl_sync(FULL, idr0, 31);
            p = __shfl_up_sync(FULL, idr1, 1); if (lane == 0) p = s;
            mk1 = __ballot_sync(FULL, idr1 != p);
            s = __shfl_sync(FULL, idr1, 31);
            p = __shfl_up_sync(FULL, idr2, 1); if (lane == 0) p = s;
            mk2 = __ballot_sync(FULL, idr2 != p);
            s = __shfl_sync(FULL, idr2, 31);
            p = __shfl_up_sync(FULL, idr3, 1); if (lane == 0) p = s;
            mk3 = __ballot_sync(FULL, idr3 != p);
        }
        const ull bm0 = (ull)mk0 | ((ull)mk1 << 32);
        const ull bm1 = (ull)mk2 | ((ull)mk3 << 32);
        // First row we own; full batches before it are skipped entirely.
        const int i0 = bm0 ? (__ffsll((long long)bm0) - 1)
                           : (bm1 ? 64 + (__ffsll((long long)bm1) - 1) : CHUNK);

        #pragma unroll
        for (int half = 0; half < 2; ++half) {
            const ull bm = half ? bm1 : bm0;
            #pragma unroll
            for (int b64 = 0; b64 < 64; b64 += BATCH) {
                const int base = half * 64 + b64;
                if (base + BATCH <= i0) continue;   // uniform: fully skipped

                // Unconditional batch of independent LDG.32 (pre-i0 rows in
                // the partial batch are discarded at the first flush).
                float v[BATCH];
                #pragma unroll
                for (int j = 0; j < BATCH; ++j)
                    v[j] = __ldcs(&fptr[(base + j) * 32]);

                const unsigned bb = (unsigned)(bm >> b64) & 0xFFu;
                if (bb == 0u) {                     // uniform: no boundary
                    float a = fmaxf(v[0], v[1]);
                    float b = fmaxf(v[2], v[3]);
                    float c = fmaxf(v[4], v[5]);
                    float d = fmaxf(v[6], v[7]);
                    m = fmaxf(m, fmaxf(fmaxf(a, b), fmaxf(c, d)));
                } else {
                    #pragma unroll
                    for (int j = 0; j < BATCH; ++j) {
                        if ((bb >> j) & 1u) {       // uniform (mask bit)
                            const int i = base + j;
                            int sel = (i < 32) ? idr0 : (i < 64) ? idr1
                                    : (i < 96) ? idr2 : idr3;
                            int nid = __shfl_sync(FULL, sel, i & 31);
                            if (resp) {
                                out[cur * 32 + lane] = m;
                                for (int g = cur + 1; g < nid; ++g)
                                    out[g * 32 + lane] = 0.0f;
                            }
                            cur  = nid;
                            m    = -CUDART_INF_F;
                            resp = true;
                        }
                        m = fmaxf(m, v[j]);
                    }
                }
            }
        }
    } else {
        // Ragged last chunk: scalar path (at most one warp in the grid).
        for (int i = 0; i < nrows; ++i) {
            int sel = (i < 32) ? idr0 : (i < 64) ? idr1
                    : (i < 96) ? idr2 : idr3;
            int id = __shfl_sync(FULL, sel, i & 31);
            if (id != cur) {
                if (resp) {
                    out[cur * 32 + lane] = m;
                    for (int g = cur + 1; g < id; ++g)
                        out[g * 32 + lane] = 0.0f;
                }
                cur  = id;
                m    = -CUDART_INF_F;
                resp = true;
            }
            m = fmaxf(m, fptr[i * 32]);
        }
    }

    // Finish the last segment we own: it may continue past the chunk end.
    int r = r0 + nrows;
    if (resp) {
        bool first = (nrows == CHUNK);
        while (r < N) {                         // uniform condition
            int rl = r + lane;
            int idn = first ? idn0 : ((rl < N) ? ids[rl] : INT_MAX);
            first = false;
            unsigned diff = __ballot_sync(FULL, idn != cur);
            int k = diff ? (__ffs(diff) - 1) : 32;   // continuation rows
            for (int j = 0; j < k; ++j)              // independent loads
                m = fmaxf(m, __ldcs(&feat[(unsigned)(r + j) * 32u + lane]));
            r += k;
            if (k < 32) break;
        }
        out[cur * 32 + lane] = m;
        int next_id = (r < N) ? ids[r] : M;
        for (int g = cur + 1; g < next_id; ++g)
            out[g * 32 + lane] = 0.0f;
    }

    // Leading gap: segments before ids[0] are empty.
    if (r0 == 0) {
        int first_id = ids[0];
        for (int g = 0; g < first_id; ++g)
            out[g * 32 + lane] = 0.0f;
    }
}

extern "C" void kernel_launch(void* const* d_in, const int* in_sizes, int n_in,
                              void* d_out, int out_size) {
    const float* feat = (const float*)d_in[0];
    const int*   ids  = (const int*)d_in[1];
    float*       out  = (float*)d_out;

    const int N = in_sizes[1];
    const int M = out_size / 32;

    const int warps   = (N + CHUNK - 1) / CHUNK;
    const int threads = 256;
    const int blocks  = (warps * 32 + threads - 1) / threads;

    seg_max_kernel<<<blocks, threads>>>(feat, ids, out, N, M);
}

// round 15
// speedup vs baseline: 1.1673x; 1.0115x over previous
#include <cuda_runtime.h>
#include <cuda_bf16.h>
#include <math_constants.h>
#include <limits.h>

// Segment-max pooling, sorted ids (N rows x 32 ch -> M segments).
// One warp owns CHUNK=64 rows; lane = channel (scalar LDG.32, BATCH=8).
// NEW: the warp fires prefetch.global.L2 for its whole 8KB slab up front --
// zero registers, zero scoreboard, full chunk in flight at DRAM immediately;
// subsequent batched LDGs hit L2 (~234cyc) instead of DRAM (~577cyc).
// Boundaries precomputed as a 64-bit ballot mask; batch fast path; skip-start
// at batch granularity (pre-boundary pollution discarded at first flush);
// responsible-warp tail scan with prefetched ids; gap segments zeroed.

#define CHUNK 64
#define BATCH 8

typedef unsigned long long ull;

__global__ __launch_bounds__(256, 8) void seg_max_kernel(
    const float* __restrict__ feat,
    const int*   __restrict__ ids,
    float*       __restrict__ out,
    int N, int M)
{
    const unsigned FULL = 0xFFFFFFFFu;
    const int lane = threadIdx.x & 31;
    const int warp = blockIdx.x * (blockDim.x >> 5) + (threadIdx.x >> 5);

    const int r0 = warp * CHUNK;               // < 4M, fits int
    if (r0 >= N) return;
    const int nrows = (N - r0 < CHUNK) ? (N - r0) : CHUNK;

    const float* fptr = feat + (unsigned)r0 * 32u + (unsigned)lane;

    // Fire-and-forget L2 prefetch of the entire chunk (no regs, no stalls).
    if (nrows == CHUNK) {
        #pragma unroll
        for (int i = 0; i < CHUNK; i += 2)      // one lane-width per 2 rows
            asm volatile("prefetch.global.L2 [%0];"
                         :: "l"(fptr + i * 32) : "memory");
        #pragma unroll
        for (int i = 1; i < CHUNK; i += 2)
            asm volatile("prefetch.global.L2 [%0];"
                         :: "l"(fptr + i * 32) : "memory");
    }

    // Coalesced chunk ids + prefetch of the 32 ids after the chunk.
    int id_lo = (lane < nrows)      ? ids[r0 + lane]      : 0;
    int id_hi = (32 + lane < nrows) ? ids[r0 + 32 + lane] : 0;
    int idn0  = (r0 + CHUNK + lane < N) ? ids[r0 + CHUNK + lane] : INT_MAX;
    const int prev_id = (r0 > 0) ? ids[r0 - 1] : -1;

    int   cur  = prev_id;
    bool  resp = false;
    float m    = -CUDART_INF_F;

    if (nrows == CHUNK) {
        // 64-bit boundary mask: bit i set iff ids[r0+i] != ids[r0+i-1].
        int p = __shfl_up_sync(FULL, id_lo, 1);
        if (lane == 0) p = prev_id;
        unsigned mlo = __ballot_sync(FULL, id_lo != p);

        int s = __shfl_sync(FULL, id_lo, 31);
        p = __shfl_up_sync(FULL, id_hi, 1);
        if (lane == 0) p = s;
        unsigned mhi = __ballot_sync(FULL, id_hi != p);

        const ull bmask = (ull)mlo | ((ull)mhi << 32);
        // First row we own; full batches before it are skipped entirely.
        const int i0 = bmask ? (__ffsll((long long)bmask) - 1) : CHUNK;

        #pragma unroll
        for (int base = 0; base < CHUNK; base += BATCH) {
            if (base + BATCH <= i0) continue;   // uniform: fully skipped

            // Unconditional batch of independent LDG.32 (pre-i0 rows in the
            // partial batch pollute m harmlessly: discarded at first flush).
            float v[BATCH];
            #pragma unroll
            for (int j = 0; j < BATCH; ++j)
                v[j] = __ldcs(&fptr[(base + j) * 32]);

            const unsigned bb = (unsigned)(bmask >> base) & 0xFFu;
            if (bb == 0u) {                     // uniform: no boundary
                float a = fmaxf(v[0], v[1]);
                float b = fmaxf(v[2], v[3]);
                float c = fmaxf(v[4], v[5]);
                float d = fmaxf(v[6], v[7]);
                m = fmaxf(m, fmaxf(fmaxf(a, b), fmaxf(c, d)));
            } else {
                #pragma unroll
                for (int j = 0; j < BATCH; ++j) {
                    if ((bb >> j) & 1u) {       // uniform (mask bit)
                        const int i = base + j;
                        int nid = __shfl_sync(FULL, (i < 32) ? id_lo : id_hi,
                                              i & 31);
                        if (resp) {
                            out[cur * 32 + lane] = m;
                            for (int g = cur + 1; g < nid; ++g)
                                out[g * 32 + lane] = 0.0f;
                        }
                        cur  = nid;
                        m    = -CUDART_INF_F;
                        resp = true;
                    }
                    m = fmaxf(m, v[j]);
                }
            }
        }
    } else {
        // Ragged last chunk: scalar path (one warp in the grid).
        for (int i = 0; i < nrows; ++i) {
            int id = __shfl_sync(FULL, (i < 32) ? id_lo : id_hi, i & 31);
            if (id != cur) {
                if (resp) {
                    out[cur * 32 + lane] = m;
                    for (int g = cur + 1; g < id; ++g)
                        out[g * 32 + lane] = 0.0f;
                }
                cur  = id;
                m    = -CUDART_INF_F;
                resp = true;
            }
            m = fmaxf(m, fptr[i * 32]);
        }
    }

    // Finish the last segment we own: it may continue past the chunk end.
    int r = r0 + nrows;
    if (resp) {
        bool first = (nrows == CHUNK);
        while (r < N) {                         // uniform condition
            int rl = r + lane;
            int idn = first ? idn0 : ((rl < N) ? ids[rl] : INT_MAX);
            first = false;
            unsigned diff = __ballot_sync(FULL, idn != cur);
            int k = diff ? (__ffs(diff) - 1) : 32;   // continuation rows
            for (int j = 0; j < k; ++j)              // independent loads
                m = fmaxf(m, __ldcs(&feat[(unsigned)(r + j) * 32u + lane]));
            r += k;
            if (k < 32) break;
        }
        out[cur * 32 + lane] = m;
        int next_id = (r < N) ? ids[r] : M;
        for (int g = cur + 1; g < next_id; ++g)
            out[g * 32 + lane] = 0.0f;
    }

    // Leading gap: segments before ids[0] are empty.
    if (r0 == 0) {
        int first_id = ids[0];
        for (int g = 0; g < first_id; ++g)
            out[g * 32 + lane] = 0.0f;
    }
}

extern "C" void kernel_launch(void* const* d_in, const int* in_sizes, int n_in,
                              void* d_out, int out_size) {
    const float* feat = (const float*)d_in[0];
    const int*   ids  = (const int*)d_in[1];
    float*       out  = (float*)d_out;

    const int N = in_sizes[1];
    const int M = out_size / 32;

    const int warps   = (N + CHUNK - 1) / CHUNK;
    const int threads = 256;
    const int blocks  = (warps * 32 + threads - 1) / threads;

    seg_max_kernel<<<blocks, threads>>>(feat, ids, out, N, M);
}

// round 16
// speedup vs baseline: 1.2729x; 1.0905x over previous
#include <cuda_runtime.h>
#include <cuda_bf16.h>
#include <math_constants.h>
#include <limits.h>

// Segment-max pooling, sorted ids (N rows x 32 ch -> M segments).
// One warp owns CHUNK=64 rows, streamed through TWO 2KB smem windows filled
// by per-lane cp.async.cg (16B/lane, 4 warp-ops per 16-row window, commit
// groups + wait_group): loads retire into smem with zero register cost and
// all 32 lanes issuing. The warp consumes window k (conflict-free LDS) while
// window k+1 streams. Boundary logic identical to the best LDG kernel:
// 64-bit ballot mask, batch fast path, responsible-warp tail scan, gaps -> 0.

#define CHUNK 64
#define WARPS_PB 8
#define WIN_BYTES 2048                    // 16 rows * 128B
#define WARP_SMEM (2 * WIN_BYTES)

typedef unsigned long long ull;

__device__ __forceinline__ unsigned smem_u32(const void* p) {
    unsigned a;
    asm("{ .reg .u64 t; cvta.to.shared.u64 t, %1; cvt.u32.u64 %0, t; }"
        : "=r"(a) : "l"(p));
    return a;
}

__device__ __forceinline__ void cp16(unsigned dst, const void* src) {
    asm volatile("cp.async.cg.shared.global [%0], [%1], 16;"
                 :: "r"(dst), "l"(src) : "memory");
}

// Issue one 16-row window (widx in 0..3) into buffer buf (0/1), as a group.
__device__ __forceinline__ void issue_window(
    unsigned sbase, int buf, const float* fchunk, int widx, int lane)
{
    const char* src = (const char*)fchunk
                    + (unsigned)(widx * 16 + (lane >> 3)) * 128u
                    + (unsigned)(lane & 7) * 16u;
    unsigned dst = sbase + buf * WIN_BYTES
                 + (unsigned)(lane >> 3) * 128u + (unsigned)(lane & 7) * 16u;
    #pragma unroll
    for (int o = 0; o < 4; ++o)
        cp16(dst + o * 512u, src + o * 512u);
    asm volatile("cp.async.commit_group;" ::: "memory");
}

__global__ __launch_bounds__(256, 7) void seg_max_kernel(
    const float* __restrict__ feat,
    const int*   __restrict__ ids,
    float*       __restrict__ out,
    int N, int M)
{
    extern __shared__ char smem[];
    const unsigned FULL = 0xFFFFFFFFu;
    const int lane = threadIdx.x & 31;
    const int wib  = threadIdx.x >> 5;
    const int warp = blockIdx.x * WARPS_PB + wib;

    const int r0 = warp * CHUNK;               // < 4M, fits int
    if (r0 >= N) return;
    const int nrows = (N - r0 < CHUNK) ? (N - r0) : CHUNK;

    const float* fchunk = feat + (unsigned)r0 * 32u;
    float*   sbuf  = (float*)(smem + wib * WARP_SMEM);
    unsigned sbase = smem_u32(sbuf);

    int   cur;
    bool  resp = false;
    float m    = -CUDART_INF_F;

    if (nrows == CHUNK) {
        // Fill the pipe first: windows 0 and 1 (no dependency on ids).
        issue_window(sbase, 0, fchunk, 0, lane);
        issue_window(sbase, 1, fchunk, 1, lane);

        // Overlap: ids (coalesced), tail prefetch, boundary mask.
        int id_lo = ids[r0 + lane];
        int id_hi = ids[r0 + 32 + lane];
        int idn0  = (r0 + CHUNK + lane < N) ? ids[r0 + CHUNK + lane] : INT_MAX;
        const int prev_id = (r0 > 0) ? ids[r0 - 1] : -1;
        cur = prev_id;

        int p = __shfl_up_sync(FULL, id_lo, 1);
        if (lane == 0) p = prev_id;
        unsigned mlo = __ballot_sync(FULL, id_lo != p);
        int s = __shfl_sync(FULL, id_lo, 31);
        p = __shfl_up_sync(FULL, id_hi, 1);
        if (lane == 0) p = s;
        unsigned mhi = __ballot_sync(FULL, id_hi != p);
        const ull bmask = (ull)mlo | ((ull)mhi << 32);

        #pragma unroll
        for (int w = 0; w < 4; ++w) {
            const int buf = w & 1;
            if (w < 3) asm volatile("cp.async.wait_group 1;" ::: "memory");
            else       asm volatile("cp.async.wait_group 0;" ::: "memory");
            __syncwarp();

            const float* sw = sbuf + buf * (WIN_BYTES / 4);

            #pragma unroll
            for (int half = 0; half < 2; ++half) {
                const int base = w * 16 + half * 8;

                float v[8];
                #pragma unroll
                for (int j = 0; j < 8; ++j)
                    v[j] = sw[(half * 8 + j) * 32 + lane]; // conflict-free

                const unsigned bb = (unsigned)(bmask >> base) & 0xFFu;
                if (bb == 0u) {                     // uniform: no boundary
                    float a = fmaxf(v[0], v[1]);
                    float b = fmaxf(v[2], v[3]);
                    float c = fmaxf(v[4], v[5]);
                    float d = fmaxf(v[6], v[7]);
                    m = fmaxf(m, fmaxf(fmaxf(a, b), fmaxf(c, d)));
                } else {
                    #pragma unroll
                    for (int j = 0; j < 8; ++j) {
                        if ((bb >> j) & 1u) {       // uniform (mask bit)
                            const int i = base + j;
                            int nid = __shfl_sync(FULL,
                                                  (i < 32) ? id_lo : id_hi,
                                                  i & 31);
                            if (resp) {
                                out[cur * 32 + lane] = m;
                                for (int g = cur + 1; g < nid; ++g)
                                    out[g * 32 + lane] = 0.0f;
                            }
                            cur  = nid;
                            m    = -CUDART_INF_F;
                            resp = true;
                        }
                        m = fmaxf(m, v[j]);
                    }
                }
            }

            // Reissue this buffer with window w+2 (after consumption).
            if (w < 2) {
                __syncwarp();
                issue_window(sbase, buf, fchunk, w + 2, lane);
            }
        }

        // Finish the last segment we own (may continue past the chunk end).
        int r = r0 + CHUNK;
        if (resp) {
            bool first = true;
            while (r < N) {                         // uniform condition
                int rl = r + lane;
                int idn = first ? idn0 : ((rl < N) ? ids[rl] : INT_MAX);
                first = false;
                unsigned diff = __ballot_sync(FULL, idn != cur);
                int k = diff ? (__ffs(diff) - 1) : 32;
                for (int j = 0; j < k; ++j)         // independent LDGs
                    m = fmaxf(m, __ldcs(&feat[(unsigned)(r + j) * 32u + lane]));
                r += k;
                if (k < 32) break;
            }
            out[cur * 32 + lane] = m;
            int next_id = (r < N) ? ids[r] : M;
            for (int g = cur + 1; g < next_id; ++g)
                out[g * 32 + lane] = 0.0f;
        }
    } else {
        // Ragged last chunk: direct-LDG scalar path (at most one warp).
        int id_lo = (lane < nrows)      ? ids[r0 + lane]      : 0;
        int id_hi = (32 + lane < nrows) ? ids[r0 + 32 + lane] : 0;
        const int prev_id = (r0 > 0) ? ids[r0 - 1] : -1;
        cur = prev_id;

        const float* fptr = feat + (unsigned)r0 * 32u + (unsigned)lane;
        for (int i = 0; i < nrows; ++i) {
            int id = __shfl_sync(FULL, (i < 32) ? id_lo : id_hi, i & 31);
            if (id != cur) {
                if (resp) {
                    out[cur * 32 + lane] = m;
                    for (int g = cur + 1; g < id; ++g)
                        out[g * 32 + lane] = 0.0f;
                }
                cur  = id;
                m    = -CUDART_INF_F;
                resp = true;
            }
            m = fmaxf(m, fptr[i * 32]);
        }
        if (resp) {
            out[cur * 32 + lane] = m;
            for (int g = cur + 1; g < M; ++g)       // trailing gap
                out[g * 32 + lane] = 0.0f;
        }
    }

    // Leading gap: segments before ids[0] are empty.
    if (r0 == 0) {
        int first_id = ids[0];
        for (int g = 0; g < first_id; ++g)
            out[g * 32 + lane] = 0.0f;
    }
}

extern "C" void kernel_launch(void* const* d_in, const int* in_sizes, int n_in,
                              void* d_out, int out_size) {
    const float* feat = (const float*)d_in[0];
    const int*   ids  = (const int*)d_in[1];
    float*       out  = (float*)d_out;

    const int N = in_sizes[1];
    const int M = out_size / 32;

    const int warps  = (N + CHUNK - 1) / CHUNK;
    const int blocks = (warps + WARPS_PB - 1) / WARPS_PB;
    const int smem_bytes = WARPS_PB * WARP_SMEM;   // 32 KB

    seg_max_kernel<<<blocks, 256, smem_bytes>>>(feat, ids, out, N, M);
}

// round 17
// speedup vs baseline: 1.2859x; 1.0102x over previous
#include <cuda_runtime.h>
#include <cuda_bf16.h>
#include <math_constants.h>
#include <limits.h>

// Segment-max pooling, sorted ids (N rows x 32 ch -> M segments).
// One warp owns CHUNK=64 rows, streamed through TWO 2KB smem windows filled
// by per-lane cp.async.cg (16B/lane, 4 warp-ops per 16-row window, commit
// groups + wait_group): loads retire into smem with zero register cost and
// all 32 lanes issuing. The warp consumes window k (conflict-free LDS) while
// window k+1 streams. NEW vs R16: kernel_launch requests the MAX shared
// memory carveout so 32KB/block fits 7 blocks/SM (87.5% occ) instead of 5.
// Boundary logic: 64-bit ballot mask, batch fast path, tail scan, gaps -> 0.

#define CHUNK 64
#define WARPS_PB 8
#define WIN_BYTES 2048                    // 16 rows * 128B
#define WARP_SMEM (2 * WIN_BYTES)

typedef unsigned long long ull;

__device__ __forceinline__ unsigned smem_u32(const void* p) {
    unsigned a;
    asm("{ .reg .u64 t; cvta.to.shared.u64 t, %1; cvt.u32.u64 %0, t; }"
        : "=r"(a) : "l"(p));
    return a;
}

__device__ __forceinline__ void cp16(unsigned dst, const void* src) {
    asm volatile("cp.async.cg.shared.global [%0], [%1], 16;"
                 :: "r"(dst), "l"(src) : "memory");
}

// Issue one 16-row window (widx in 0..3) into buffer buf (0/1), as a group.
__device__ __forceinline__ void issue_window(
    unsigned sbase, int buf, const float* fchunk, int widx, int lane)
{
    const char* src = (const char*)fchunk
                    + (unsigned)(widx * 16 + (lane >> 3)) * 128u
                    + (unsigned)(lane & 7) * 16u;
    unsigned dst = sbase + buf * WIN_BYTES
                 + (unsigned)(lane >> 3) * 128u + (unsigned)(lane & 7) * 16u;
    #pragma unroll
    for (int o = 0; o < 4; ++o)
        cp16(dst + o * 512u, src + o * 512u);
    asm volatile("cp.async.commit_group;" ::: "memory");
}

__global__ __launch_bounds__(256, 7) void seg_max_kernel(
    const float* __restrict__ feat,
    const int*   __restrict__ ids,
    float*       __restrict__ out,
    int N, int M)
{
    extern __shared__ char smem[];
    const unsigned FULL = 0xFFFFFFFFu;
    const int lane = threadIdx.x & 31;
    const int wib  = threadIdx.x >> 5;
    const int warp = blockIdx.x * WARPS_PB + wib;

    const int r0 = warp * CHUNK;               // < 4M, fits int
    if (r0 >= N) return;
    const int nrows = (N - r0 < CHUNK) ? (N - r0) : CHUNK;

    const float* fchunk = feat + (unsigned)r0 * 32u;
    float*   sbuf  = (float*)(smem + wib * WARP_SMEM);
    unsigned sbase = smem_u32(sbuf);

    int   cur;
    bool  resp = false;
    float m    = -CUDART_INF_F;

    if (nrows == CHUNK) {
        // Fill the pipe first: windows 0 and 1 (no dependency on ids).
        issue_window(sbase, 0, fchunk, 0, lane);
        issue_window(sbase, 1, fchunk, 1, lane);

        // Overlap: ids (coalesced), tail prefetch, boundary mask.
        int id_lo = ids[r0 + lane];
        int id_hi = ids[r0 + 32 + lane];
        int idn0  = (r0 + CHUNK + lane < N) ? ids[r0 + CHUNK + lane] : INT_MAX;
        const int prev_id = (r0 > 0) ? ids[r0 - 1] : -1;
        cur = prev_id;

        int p = __shfl_up_sync(FULL, id_lo, 1);
        if (lane == 0) p = prev_id;
        unsigned mlo = __ballot_sync(FULL, id_lo != p);
        int s = __shfl_sync(FULL, id_lo, 31);
        p = __shfl_up_sync(FULL, id_hi, 1);
        if (lane == 0) p = s;
        unsigned mhi = __ballot_sync(FULL, id_hi != p);
        const ull bmask = (ull)mlo | ((ull)mhi << 32);

        #pragma unroll
        for (int w = 0; w < 4; ++w) {
            const int buf = w & 1;
            if (w < 3) asm volatile("cp.async.wait_group 1;" ::: "memory");
            else       asm volatile("cp.async.wait_group 0;" ::: "memory");
            __syncwarp();

            const float* sw = sbuf + buf * (WIN_BYTES / 4);

            #pragma unroll
            for (int half = 0; half < 2; ++half) {
                const int base = w * 16 + half * 8;

                float v[8];
                #pragma unroll
                for (int j = 0; j < 8; ++j)
                    v[j] = sw[(half * 8 + j) * 32 + lane]; // conflict-free

                const unsigned bb = (unsigned)(bmask >> base) & 0xFFu;
                if (bb == 0u) {                     // uniform: no boundary
                    float a = fmaxf(v[0], v[1]);
                    float b = fmaxf(v[2], v[3]);
                    float c = fmaxf(v[4], v[5]);
                    float d = fmaxf(v[6], v[7]);
                    m = fmaxf(m, fmaxf(fmaxf(a, b), fmaxf(c, d)));
                } else {
                    #pragma unroll
                    for (int j = 0; j < 8; ++j) {
                        if ((bb >> j) & 1u) {       // uniform (mask bit)
                            const int i = base + j;
                            int nid = __shfl_sync(FULL,
                                                  (i < 32) ? id_lo : id_hi,
                                                  i & 31);
                            if (resp) {
                                out[cur * 32 + lane] = m;
                                for (int g = cur + 1; g < nid; ++g)
                                    out[g * 32 + lane] = 0.0f;
                            }
                            cur  = nid;
                            m    = -CUDART_INF_F;
                            resp = true;
                        }
                        m = fmaxf(m, v[j]);
                    }
                }
            }

            // Reissue this buffer with window w+2 (after consumption).
            if (w < 2) {
                __syncwarp();
                issue_window(sbase, buf, fchunk, w + 2, lane);
            }
        }

        // Finish the last segment we own (may continue past the chunk end).
        int r = r0 + CHUNK;
        if (resp) {
            bool first = true;
            while (r < N) {                         // uniform condition
                int rl = r + lane;
                int idn = first ? idn0 : ((rl < N) ? ids[rl] : INT_MAX);
                first = false;
                unsigned diff = __ballot_sync(FULL, idn != cur);
                int k = diff ? (__ffs(diff) - 1) : 32;
                for (int j = 0; j < k; ++j)         // independent LDGs
                    m = fmaxf(m, __ldcs(&feat[(unsigned)(r + j) * 32u + lane]));
                r += k;
                if (k < 32) break;
            }
            out[cur * 32 + lane] = m;
            int next_id = (r < N) ? ids[r] : M;
            for (int g = cur + 1; g < next_id; ++g)
                out[g * 32 + lane] = 0.0f;
        }
    } else {
        // Ragged last chunk: direct-LDG scalar path (at most one warp).
        int id_lo = (lane < nrows)      ? ids[r0 + lane]      : 0;
        int id_hi = (32 + lane < nrows) ? ids[r0 + 32 + lane] : 0;
        const int prev_id = (r0 > 0) ? ids[r0 - 1] : -1;
        cur = prev_id;

        const float* fptr = feat + (unsigned)r0 * 32u + (unsigned)lane;
        for (int i = 0; i < nrows; ++i) {
            int id = __shfl_sync(FULL, (i < 32) ? id_lo : id_hi, i & 31);
            if (id != cur) {
                if (resp) {
                    out[cur * 32 + lane] = m;
                    for (int g = cur + 1; g < id; ++g)
                        out[g * 32 + lane] = 0.0f;
                }
                cur  = id;
                m    = -CUDART_INF_F;
                resp = true;
            }
            m = fmaxf(m, fptr[i * 32]);
        }
        if (resp) {
            out[cur * 32 + lane] = m;
            for (int g = cur + 1; g < M; ++g)       // trailing gap
                out[g * 32 + lane] = 0.0f;
        }
    }

    // Leading gap: segments before ids[0] are empty.
    if (r0 == 0) {
        int first_id = ids[0];
        for (int g = 0; g < first_id; ++g)
            out[g * 32 + lane] = 0.0f;
    }
}

extern "C" void kernel_launch(void* const* d_in, const int* in_sizes, int n_in,
                              void* d_out, int out_size) {
    const float* feat = (const float*)d_in[0];
    const int*   ids  = (const int*)d_in[1];
    float*       out  = (float*)d_out;

    const int N = in_sizes[1];
    const int M = out_size / 32;

    // Request the maximum L1/shared carveout so 32KB/block packs 7 blocks/SM.
    // Idempotent, allocation-free, not a stream op (graph-capture safe).
    cudaFuncSetAttribute(seg_max_kernel,
                         cudaFuncAttributePreferredSharedMemoryCarveout,
                         cudaSharedmemCarveoutMaxShared);
    cudaFuncSetAttribute(seg_max_kernel,
                         cudaFuncAttributeMaxDynamicSharedMemorySize,
                         WARPS_PB * WARP_SMEM);

    const int warps  = (N + CHUNK - 1) / CHUNK;
    const int blocks = (warps + WARPS_PB - 1) / WARPS_PB;
    const int smem_bytes = WARPS_PB * WARP_SMEM;   // 32 KB

    seg_max_kernel<<<blocks, 256, smem_bytes>>>(feat, ids, out, N, M);
}